// round 1
// baseline (speedup 1.0000x reference)
#include <cuda_runtime.h>
#include <cuda_bf16.h>
#include <math.h>

#define N_ROIS 128
#define BEV_H 188
#define BEV_W 188
#define BEV_C 256
#define PTS_PER_BLOCK 8
#define THREADS 256

// mask radius constant
#define SAMPLE_RADIUS 2.4f

__global__ void __launch_bounds__(THREADS)
vsa_fused_kernel(const float* __restrict__ points,
                 const float* __restrict__ rois,
                 const float* __restrict__ bev,
                 float* __restrict__ out,
                 int n)
{
    // Shared ROI staging, SoA layout: [field][roi]
    __shared__ float s_roi[7][N_ROIS];

    // Load 128*7 = 896 floats with 256 threads (transpose AoS->SoA)
    for (int i = threadIdx.x; i < N_ROIS * 7; i += THREADS) {
        int r = i / 7;
        int f = i - r * 7;
        s_roi[f][r] = rois[i];
    }
    __syncthreads();

    const int warp = threadIdx.x >> 5;
    const int lane = threadIdx.x & 31;
    const int p = blockIdx.x * PTS_PER_BLOCK + warp;
    if (p >= n) return;

    const unsigned FULL = 0xFFFFFFFFu;

    // --- load point (broadcast via cache) ---
    const float px = points[p * 3 + 0];
    const float py = points[p * 3 + 1];
    const float pz = points[p * 3 + 2];

    // --- distance + argmin over 128 ROIs: 4 per lane, sequential (keeps
    //     first-occurrence-of-min semantics like jnp.argmin) ---
    float best = INFINITY;
    int bidx = N_ROIS;  // sentinel larger than any real idx
    const int rbase = lane * 4;
    #pragma unroll
    for (int k = 0; k < 4; k++) {
        const int r = rbase + k;
        const float dx = px - s_roi[0][r];
        const float dy = py - s_roi[1][r];
        const float dz = pz - s_roi[2][r];
        const float d2 = dx * dx + dy * dy + dz * dz;
        if (d2 < best) { best = d2; bidx = r; }
    }
    // shuffle argmin reduce; ties -> lower index (== first occurrence)
    #pragma unroll
    for (int off = 16; off > 0; off >>= 1) {
        const float ob = __shfl_down_sync(FULL, best, off);
        const int   oi = __shfl_down_sync(FULL, bidx, off);
        if (ob < best || (ob == best && oi < bidx)) { best = ob; bidx = oi; }
    }
    best = __shfl_sync(FULL, best, 0);
    bidx = __shfl_sync(FULL, bidx, 0);

    const float min_dis = sqrtf(best);
    // roi_max_dim = || dims/2 ||
    const float hl = s_roi[3][bidx] * 0.5f;
    const float hw = s_roi[4][bidx] * 0.5f;
    const float hh = s_roi[5][bidx] * 0.5f;
    const float roi_max_dim = sqrtf(hl * hl + hw * hw + hh * hh);
    const bool mask = min_dis < (roi_max_dim + SAMPLE_RADIUS);

    float4* op = reinterpret_cast<float4*>(out + (size_t)p * BEV_C);

    if (!mask) {
        // masked-out point: dense zero output, no gathers
        const float4 z = make_float4(0.f, 0.f, 0.f, 0.f);
        op[lane]      = z;
        op[lane + 32] = z;
        return;
    }

    // --- bilinear coords (bit-faithful to reference: two fp32 divides) ---
    const float xi = (px - 0.0f)   / 0.05f / 8.0f;
    const float yi = (py - -40.0f) / 0.05f / 8.0f;

    const int xf = (int)floorf(xi);
    const int yf = (int)floorf(yi);
    const int x0 = min(max(xf,     0), BEV_W - 1);
    const int x1 = min(max(xf + 1, 0), BEV_W - 1);
    const int y0 = min(max(yf,     0), BEV_H - 1);
    const int y1 = min(max(yf + 1, 0), BEV_H - 1);

    const float x0f = (float)x0, x1f = (float)x1;
    const float y0f = (float)y0, y1f = (float)y1;
    const float wa = (x1f - xi) * (y1f - yi);
    const float wb = (x1f - xi) * (yi - y0f);
    const float wc = (xi - x0f) * (y1f - yi);
    const float wd = (xi - x0f) * (yi - y0f);

    const float4* A = reinterpret_cast<const float4*>(bev + ((size_t)y0 * BEV_W + x0) * BEV_C);
    const float4* B = reinterpret_cast<const float4*>(bev + ((size_t)y1 * BEV_W + x0) * BEV_C);
    const float4* Cc= reinterpret_cast<const float4*>(bev + ((size_t)y0 * BEV_W + x1) * BEV_C);
    const float4* D = reinterpret_cast<const float4*>(bev + ((size_t)y1 * BEV_W + x1) * BEV_C);

    #pragma unroll
    for (int k = 0; k < 2; k++) {
        const int c4 = lane + k * 32;   // float4 index: covers 256 floats
        const float4 a = A[c4];
        const float4 b = B[c4];
        const float4 c = Cc[c4];
        const float4 d = D[c4];
        float4 o;
        o.x = a.x * wa + b.x * wb + c.x * wc + d.x * wd;
        o.y = a.y * wa + b.y * wb + c.y * wc + d.y * wd;
        o.z = a.z * wa + b.z * wb + c.z * wc + d.z * wd;
        o.w = a.w * wa + b.w * wb + c.w * wc + d.w * wd;
        op[c4] = o;
    }
}

extern "C" void kernel_launch(void* const* d_in, const int* in_sizes, int n_in,
                              void* d_out, int out_size)
{
    const float* points = (const float*)d_in[0];
    const float* rois   = (const float*)d_in[1];
    const float* bev    = (const float*)d_in[2];
    float* out = (float*)d_out;

    const int n = in_sizes[0] / 3;
    const int blocks = (n + PTS_PER_BLOCK - 1) / PTS_PER_BLOCK;
    vsa_fused_kernel<<<blocks, THREADS>>>(points, rois, bev, out, n);
}

// round 3
// speedup vs baseline: 1.0479x; 1.0479x over previous
#include <cuda_runtime.h>
#include <cuda_bf16.h>
#include <math.h>

#define N_ROIS 128
#define BEV_H 188
#define BEV_W 188
#define BEV_C 256
#define PTS_PER_BLOCK 8
#define THREADS 256

#define SAMPLE_RADIUS 2.4f

__global__ void __launch_bounds__(THREADS)
vsa_fused_kernel(const float* __restrict__ points,
                 const float* __restrict__ rois,
                 const float* __restrict__ bev,
                 float* __restrict__ out,
                 int n)
{
    // Shared ROI staging, SoA layout: [field][roi]
    __shared__ float s_roi[7][N_ROIS];

    for (int i = threadIdx.x; i < N_ROIS * 7; i += THREADS) {
        int r = i / 7;
        int f = i - r * 7;
        s_roi[f][r] = rois[i];
    }
    __syncthreads();

    const int warp = threadIdx.x >> 5;
    const int lane = threadIdx.x & 31;
    const int p = blockIdx.x * PTS_PER_BLOCK + warp;
    if (p >= n) return;

    const unsigned FULL = 0xFFFFFFFFu;

    const float px = points[p * 3 + 0];
    const float py = points[p * 3 + 1];
    const float pz = points[p * 3 + 2];

    // --- distance + argmin over 128 ROIs: 4 per lane, CONFLICT-FREE
    //     stride-1 smem access: lane reads r = lane + 32*j ---
    float best = INFINITY;
    int bidx = N_ROIS;  // sentinel
    #pragma unroll
    for (int j = 0; j < 4; j++) {
        const int r = lane + j * 32;          // stride-1 across the warp
        const float dx = px - s_roi[0][r];
        const float dy = py - s_roi[1][r];
        const float dz = pz - s_roi[2][r];
        const float d2 = dx * dx + dy * dy + dz * dz;
        // within-lane r increases with j -> '<' keeps lowest idx on ties
        if (d2 < best) { best = d2; bidx = r; }
    }
    // shuffle argmin reduce; lexicographic (d2, idx) -> first occurrence
    #pragma unroll
    for (int off = 16; off > 0; off >>= 1) {
        const float ob = __shfl_down_sync(FULL, best, off);
        const int   oi = __shfl_down_sync(FULL, bidx, off);
        if (ob < best || (ob == best && oi < bidx)) { best = ob; bidx = oi; }
    }
    best = __shfl_sync(FULL, best, 0);
    bidx = __shfl_sync(FULL, bidx, 0);

    const float min_dis = sqrtf(best);
    const float hl = s_roi[3][bidx] * 0.5f;   // broadcast (same addr all lanes)
    const float hw = s_roi[4][bidx] * 0.5f;
    const float hh = s_roi[5][bidx] * 0.5f;
    const float roi_max_dim = sqrtf(hl * hl + hw * hw + hh * hh);
    const bool mask = min_dis < (roi_max_dim + SAMPLE_RADIUS);

    float4* op = reinterpret_cast<float4*>(out + (size_t)p * BEV_C);

    if (!mask) {
        const float4 z = make_float4(0.f, 0.f, 0.f, 0.f);
        __stcs(&op[lane],      z);
        __stcs(&op[lane + 32], z);
        return;
    }

    // --- bilinear coords (bit-faithful: two fp32 divides, floor, clamp) ---
    const float xi = (px - 0.0f)   / 0.05f / 8.0f;
    const float yi = (py - -40.0f) / 0.05f / 8.0f;

    const int xf = (int)floorf(xi);
    const int yf = (int)floorf(yi);
    const int x0 = min(max(xf,     0), BEV_W - 1);
    const int x1 = min(max(xf + 1, 0), BEV_W - 1);
    const int y0 = min(max(yf,     0), BEV_H - 1);
    const int y1 = min(max(yf + 1, 0), BEV_H - 1);

    const float x0f = (float)x0, x1f = (float)x1;
    const float y0f = (float)y0, y1f = (float)y1;
    const float wa = (x1f - xi) * (y1f - yi);
    const float wb = (x1f - xi) * (yi - y0f);
    const float wc = (xi - x0f) * (y1f - yi);
    const float wd = (xi - x0f) * (yi - y0f);

    const float4* A = reinterpret_cast<const float4*>(bev + ((size_t)y0 * BEV_W + x0) * BEV_C);
    const float4* B = reinterpret_cast<const float4*>(bev + ((size_t)y1 * BEV_W + x0) * BEV_C);
    const float4* Cc= reinterpret_cast<const float4*>(bev + ((size_t)y0 * BEV_W + x1) * BEV_C);
    const float4* D = reinterpret_cast<const float4*>(bev + ((size_t)y1 * BEV_W + x1) * BEV_C);

    // Batch ALL 8 corner loads first (MLP=8), then FMAs, then 2 stores.
    const int c0 = lane;
    const int c1 = lane + 32;
    const float4 a0 = A[c0];
    const float4 b0 = B[c0];
    const float4 e0 = Cc[c0];
    const float4 d0 = D[c0];
    const float4 a1 = A[c1];
    const float4 b1 = B[c1];
    const float4 e1 = Cc[c1];
    const float4 d1 = D[c1];

    float4 o0, o1;
    o0.x = a0.x * wa + b0.x * wb + e0.x * wc + d0.x * wd;
    o0.y = a0.y * wa + b0.y * wb + e0.y * wc + d0.y * wd;
    o0.z = a0.z * wa + b0.z * wb + e0.z * wc + d0.z * wd;
    o0.w = a0.w * wa + b0.w * wb + e0.w * wc + d0.w * wd;
    o1.x = a1.x * wa + b1.x * wb + e1.x * wc + d1.x * wd;
    o1.y = a1.y * wa + b1.y * wb + e1.y * wc + d1.y * wd;
    o1.z = a1.z * wa + b1.z * wb + e1.z * wc + d1.z * wd;
    o1.w = a1.w * wa + b1.w * wb + e1.w * wc + d1.w * wd;

    __stcs(&op[c0], o0);
    __stcs(&op[c1], o1);
}

extern "C" void kernel_launch(void* const* d_in, const int* in_sizes, int n_in,
                              void* d_out, int out_size)
{
    const float* points = (const float*)d_in[0];
    const float* rois   = (const float*)d_in[1];
    const float* bev    = (const float*)d_in[2];
    float* out = (float*)d_out;

    const int n = in_sizes[0] / 3;
    const int blocks = (n + PTS_PER_BLOCK - 1) / PTS_PER_BLOCK;
    vsa_fused_kernel<<<blocks, THREADS>>>(points, rois, bev, out, n);
}

// round 4
// speedup vs baseline: 1.3352x; 1.2741x over previous
#include <cuda_runtime.h>
#include <cuda_bf16.h>
#include <math.h>

#define N_ROIS 128
#define BEV_H 188
#define BEV_W 188
#define BEV_C 256
#define THREADS 256
#define WARPS 8

__global__ void __launch_bounds__(THREADS)
vsa_fused_kernel(const float* __restrict__ points,
                 const float* __restrict__ rois,
                 const float* __restrict__ bev,
                 float* __restrict__ out,
                 int n)
{
    // ROI cache: (cx, cy, cz, radius = ||dims/2|| + 2.4)
    __shared__ float4 s_roi[N_ROIS];
    // Phase-1 -> phase-2 handoff, per warp per point
    __shared__ float4 s_wt[WARPS][32];   // bilinear weights
    __shared__ int4   s_off[WARPS][32];  // x0,x1,y0,y1 ; x0=-1 zero, x0=-2 skip

    if (threadIdx.x < N_ROIS) {
        const float* rp = rois + threadIdx.x * 7;
        const float hl = rp[3] * 0.5f;
        const float hw = rp[4] * 0.5f;
        const float hh = rp[5] * 0.5f;
        const float rad = sqrtf(hl * hl + hw * hw + hh * hh) + 2.4f;
        s_roi[threadIdx.x] = make_float4(rp[0], rp[1], rp[2], rad);
    }
    __syncthreads();

    const int w    = threadIdx.x >> 5;
    const int lane = threadIdx.x & 31;
    const int p    = blockIdx.x * THREADS + threadIdx.x;
    const bool valid = p < n;

    // ---------------- Phase 1: thread-per-point argmin ----------------
    float px = 0.f, py = 0.f, pz = 0.f;
    if (valid) {
        px = points[p * 3 + 0];
        py = points[p * 3 + 1];
        pz = points[p * 3 + 2];
    }

    float best = INFINITY;
    int bidx = 0;
    #pragma unroll 4
    for (int r = 0; r < N_ROIS; r++) {
        const float4 q = s_roi[r];     // warp-broadcast LDS.128
        const float dx = px - q.x;
        const float dy = py - q.y;
        const float dz = pz - q.z;
        const float d2 = dx * dx + dy * dy + dz * dz;
        // strict '<' with ascending r == first occurrence (jnp.argmin)
        if (d2 < best) { best = d2; bidx = r; }
    }
    const float rad  = s_roi[bidx].w;
    const bool  mask = valid && (sqrtf(best) < rad);

    int4   off;
    float4 wt = make_float4(0.f, 0.f, 0.f, 0.f);
    if (!valid) {
        off = make_int4(-2, 0, 0, 0);
    } else if (!mask) {
        off = make_int4(-1, 0, 0, 0);
    } else {
        // bit-faithful coords: two fp32 divides, floor, clamp
        const float xi = (px - 0.0f)   / 0.05f / 8.0f;
        const float yi = (py - -40.0f) / 0.05f / 8.0f;
        const int xf = (int)floorf(xi);
        const int yf = (int)floorf(yi);
        const int x0 = min(max(xf,     0), BEV_W - 1);
        const int x1 = min(max(xf + 1, 0), BEV_W - 1);
        const int y0 = min(max(yf,     0), BEV_H - 1);
        const int y1 = min(max(yf + 1, 0), BEV_H - 1);
        const float x0f = (float)x0, x1f = (float)x1;
        const float y0f = (float)y0, y1f = (float)y1;
        wt.x = (x1f - xi) * (y1f - yi);   // wa
        wt.y = (x1f - xi) * (yi - y0f);   // wb
        wt.z = (xi - x0f) * (y1f - yi);   // wc
        wt.w = (xi - x0f) * (yi - y0f);   // wd
        off = make_int4(x0, x1, y0, y1);
    }
    s_off[w][lane] = off;
    s_wt[w][lane]  = wt;
    __syncwarp();

    // ---------------- Phase 2: warp-per-point gather ----------------
    const int pbase = blockIdx.x * THREADS + w * 32;
    for (int i = 0; i < 32; i++) {
        const int4 o = s_off[w][i];            // warp-broadcast
        if (o.x == -2) continue;               // uniform across warp

        float4* op = reinterpret_cast<float4*>(out + (size_t)(pbase + i) * BEV_C);

        if (o.x == -1) {
            const float4 z = make_float4(0.f, 0.f, 0.f, 0.f);
            __stcs(op + lane,      z);
            __stcs(op + lane + 32, z);
            continue;
        }

        const float4 wv = s_wt[w][i];          // warp-broadcast
        const float4* A  = reinterpret_cast<const float4*>(bev + ((size_t)o.z * BEV_W + o.x) * BEV_C);
        const float4* B  = reinterpret_cast<const float4*>(bev + ((size_t)o.w * BEV_W + o.x) * BEV_C);
        const float4* Cc = reinterpret_cast<const float4*>(bev + ((size_t)o.z * BEV_W + o.y) * BEV_C);
        const float4* D  = reinterpret_cast<const float4*>(bev + ((size_t)o.w * BEV_W + o.y) * BEV_C);

        // Batch all 8 corner loads (L2-only: no L1 allocation for 0-reuse data)
        const float4 a0 = __ldcg(A  + lane);
        const float4 b0 = __ldcg(B  + lane);
        const float4 c0 = __ldcg(Cc + lane);
        const float4 d0 = __ldcg(D  + lane);
        const float4 a1 = __ldcg(A  + lane + 32);
        const float4 b1 = __ldcg(B  + lane + 32);
        const float4 c1 = __ldcg(Cc + lane + 32);
        const float4 d1 = __ldcg(D  + lane + 32);

        float4 o0, o1;
        o0.x = a0.x * wv.x + b0.x * wv.y + c0.x * wv.z + d0.x * wv.w;
        o0.y = a0.y * wv.x + b0.y * wv.y + c0.y * wv.z + d0.y * wv.w;
        o0.z = a0.z * wv.x + b0.z * wv.y + c0.z * wv.z + d0.z * wv.w;
        o0.w = a0.w * wv.x + b0.w * wv.y + c0.w * wv.z + d0.w * wv.w;
        o1.x = a1.x * wv.x + b1.x * wv.y + c1.x * wv.z + d1.x * wv.w;
        o1.y = a1.y * wv.x + b1.y * wv.y + c1.y * wv.z + d1.y * wv.w;
        o1.z = a1.z * wv.x + b1.z * wv.y + c1.z * wv.z + d1.z * wv.w;
        o1.w = a1.w * wv.x + b1.w * wv.y + c1.w * wv.z + d1.w * wv.w;

        __stcs(op + lane,      o0);
        __stcs(op + lane + 32, o1);
    }
}

extern "C" void kernel_launch(void* const* d_in, const int* in_sizes, int n_in,
                              void* d_out, int out_size)
{
    const float* points = (const float*)d_in[0];
    const float* rois   = (const float*)d_in[1];
    const float* bev    = (const float*)d_in[2];
    float* out = (float*)d_out;

    const int n = in_sizes[0] / 3;
    const int blocks = (n + THREADS - 1) / THREADS;
    vsa_fused_kernel<<<blocks, THREADS>>>(points, rois, bev, out, n);
}